// round 6
// baseline (speedup 1.0000x reference)
#include <cuda_runtime.h>
#include <cuda_fp16.h>
#include <cstdint>

#define NROWS   262144
#define NSEG    1024
#define HID     256
#define KDIM    256
#define NTILES  (NROWS / 128)

// ---------------- scratch (device globals: no allocations allowed) ----------
__device__ float  g_scores[NROWS];
__device__ __half g_w1t[HID * KDIM];          // W1^T as fp16, [n][k]
__device__ __half g_xh[(size_t)NROWS * KDIM]; // fp16 copy of x (written by k_scores)
__device__ int    g_segstart[NSEG + 1];

// ---------------- helpers ----------------------------------------------------
static __device__ __forceinline__ uint32_t smem_u32(const void* p) {
    uint32_t a;
    asm("{ .reg .u64 t; cvta.to.shared.u64 t, %1; cvt.u32.u64 %0, t; }"
        : "=r"(a) : "l"(p));
    return a;
}

static __device__ __forceinline__ void ldsm_x4(uint32_t a, uint32_t& r0, uint32_t& r1,
                                               uint32_t& r2, uint32_t& r3) {
    asm volatile("ldmatrix.sync.aligned.m8n8.x4.shared.b16 {%0,%1,%2,%3}, [%4];"
                 : "=r"(r0), "=r"(r1), "=r"(r2), "=r"(r3) : "r"(a));
}

static __device__ __forceinline__ void mma_f16(float* c,
                                               uint32_t a0, uint32_t a1, uint32_t a2, uint32_t a3,
                                               uint32_t b0, uint32_t b1) {
    asm volatile("mma.sync.aligned.m16n8k16.row.col.f32.f16.f16.f32 "
                 "{%0,%1,%2,%3}, {%4,%5,%6,%7}, {%8,%9}, {%0,%1,%2,%3};"
                 : "+f"(c[0]), "+f"(c[1]), "+f"(c[2]), "+f"(c[3])
                 : "r"(a0), "r"(a1), "r"(a2), "r"(a3), "r"(b0), "r"(b1));
}

static __device__ __forceinline__ uint32_t pack_h2(float a, float b) {
    __half2 h = __floats2half2_rn(a, b);
    return *(uint32_t*)&h;
}

// ---------------- kernel 1: W1^T -> fp16 [n][k] ------------------------------
__global__ void k_w1t(const float* __restrict__ W1) {
    int k = blockIdx.x, n = threadIdx.x;
    g_w1t[n * KDIM + k] = __float2half_rn(W1[k * HID + n]);
}

// ---------------- kernel 2: segment boundaries (batch sorted) ----------------
__global__ void k_bounds(const void* __restrict__ batch_raw) {
    const int* b32 = (const int*)batch_raw;
    bool is64 = (b32[NROWS - 1] == 0) && (b32[NROWS - 3] == 0) &&
                (b32[NROWS - 5] == 0) && (b32[NROWS - 7] == 0);
    int g = blockIdx.x * blockDim.x + threadIdx.x;
    if (g > NSEG) return;
    int lo = 0, hi = NROWS;
    while (lo < hi) {
        int mid = (lo + hi) >> 1;
        long long v = is64 ? ((const long long*)batch_raw)[mid] : (long long)b32[mid];
        if (v < (long long)g) lo = mid + 1; else hi = mid;
    }
    g_segstart[g] = lo;
}

// ---------------- kernel 3: persistent pipelined scores ----------------------
// grid = #SMs, 512 threads. Per tile: M=128, N=256 (4 chunks of 64), K=256.
// A double-buffered (next tile staged during current MMAs), B double-buffered.
#define SM_A0  0          // 128x256 fp16 swizzled       (65536)
#define SM_A1  65536      //                              (65536)
#define SM_B0  131072     // 64x256 fp16 chunk            (32768)
#define SM_B1B 163840     //                              (32768)
#define SM_SC  196608     // 128 f32 partial scores       (512)
#define SM_B1  197120     // 256 f32                      (1024)
#define SM_W2  198144     // 256 f32                      (1024)
#define SMEM_SCORES_TOTAL 199168

__global__ void __launch_bounds__(512, 1)
k_scores(const float* __restrict__ x, const float* __restrict__ b1,
         const float* __restrict__ W2, const float* __restrict__ b2) {
    extern __shared__ char smem[];
    uint32_t sb = smem_u32(smem);
    int tid = threadIdx.x, wid = tid >> 5, lid = tid & 31;
    int mw = wid & 3, nw = wid >> 2;              // warp grid: 4 (M) x 4 (N)
    int stride = gridDim.x;

    // constants
    if (tid < 128) ((float*)(smem + SM_SC))[tid] = 0.f;
    if (tid < 256) {
        ((float*)(smem + SM_B1))[tid] = b1[tid];
        ((float*)(smem + SM_W2))[tid] = W2[tid];
    }
    float b2v = __ldg(b2);

    const uint4* wp = (const uint4*)g_w1t;        // 2048 uint4 per 64-row chunk

    // ---- prologue: stage A(tile0) into A0 + write g_xh; prefetch B ch0 ----
    int tile = blockIdx.x;
    {
        const float4* xp = (const float4*)(x + (size_t)tile * 128 * 256);
        uint4* xo = (uint4*)(g_xh + (size_t)tile * 128 * 256);
        #pragma unroll
        for (int i = 0; i < 8; i++) {
            int cid = tid + i * 512;              // 0..4095
            int row = cid >> 5, c = cid & 31;
            float4 v0 = __ldg(&xp[row * 64 + c * 2]);
            float4 v1 = __ldg(&xp[row * 64 + c * 2 + 1]);
            uint4 hv;
            hv.x = pack_h2(v0.x, v0.y); hv.y = pack_h2(v0.z, v0.w);
            hv.z = pack_h2(v1.x, v1.y); hv.w = pack_h2(v1.z, v1.w);
            *(uint4*)(smem + SM_A0 + row * 512 + ((c ^ (row & 7)) << 4)) = hv;
            xo[row * 32 + c] = hv;
        }
    }
    uint4 breg[4];
    #pragma unroll
    for (int i = 0; i < 4; i++) breg[i] = wp[tid + i * 512];
    __syncthreads();

    // ---- per-lane fragment invariants ----
    int g = lid >> 2, t = lid & 3, r8 = lid & 7, j = lid >> 3;
    int arow = mw * 32 + (j & 1) * 8 + r8;
    uint32_t aoff = arow * 512;
    int arm = arow & 7, ac0 = j >> 1;
    int nloc = nw * 16 + (j >> 1) * 8 + r8;
    uint32_t boff = nloc * 512;
    int bnm = nloc & 7, bc0 = j & 1;

    const float* smB1 = (const float*)(smem + SM_B1);
    const float* smW2 = (const float*)(smem + SM_W2);
    float* sc = (float*)(smem + SM_SC);

    int cur = 0;
    for (; tile < NTILES; tile += stride) {
        int nxt = tile + stride;
        bool havenext = nxt < NTILES;
        const float4* xpn = (const float4*)(x + (size_t)nxt * 128 * 256);
        uint4* xon = (uint4*)(g_xh + (size_t)nxt * 128 * 256);
        uint32_t abase = cur ? SM_A1 : SM_A0;
        uint32_t anext = cur ? SM_A0 : SM_A1;
        float part[4] = {0.f, 0.f, 0.f, 0.f};

        for (int ch = 0; ch < 4; ch++) {
            uint32_t bbase = (ch & 1) ? SM_B1B : SM_B0;
            // commit prefetched B chunk
            #pragma unroll
            for (int i = 0; i < 4; i++) {
                int cid = tid + i * 512;
                int nl = cid >> 5, c = cid & 31;
                *(uint4*)(smem + bbase + nl * 512 + ((c ^ (nl & 7)) << 4)) = breg[i];
            }
            // prefetch next B chunk (latency hidden under MMA)
            #pragma unroll
            for (int i = 0; i < 4; i++)
                breg[i] = wp[((ch + 1) & 3) * 2048 + tid + i * 512];
            // issue next tile's A quarter loads (rows ch*32..ch*32+31)
            float4 av0a, av1a, av0b, av1b;
            int rowA = 0, cA = 0, rowB = 0, cB = 0;
            if (havenext) {
                int cid0 = ch * 1024 + tid;
                rowA = cid0 >> 5; cA = cid0 & 31;
                av0a = __ldg(&xpn[rowA * 64 + cA * 2]);
                av1a = __ldg(&xpn[rowA * 64 + cA * 2 + 1]);
                int cid1 = cid0 + 512;
                rowB = cid1 >> 5; cB = cid1 & 31;
                av0b = __ldg(&xpn[rowB * 64 + cB * 2]);
                av1b = __ldg(&xpn[rowB * 64 + cB * 2 + 1]);
            }
            __syncthreads();                      // B committed by all

            float acc[2][2][4];
            #pragma unroll
            for (int a = 0; a < 2; a++)
                #pragma unroll
                for (int b = 0; b < 2; b++)
                    #pragma unroll
                    for (int cc = 0; cc < 4; cc++) acc[a][b][cc] = 0.f;

            #pragma unroll 8
            for (int ks = 0; ks < 16; ks++) {
                uint32_t sa = (uint32_t)(((2 * ks + ac0) ^ arm) << 4);
                uint32_t so = (uint32_t)(((2 * ks + bc0) ^ bnm) << 4);
                uint32_t a0[4], a1[4], bb[4];
                ldsm_x4(sb + abase + aoff + sa,        a0[0], a0[1], a0[2], a0[3]);
                ldsm_x4(sb + abase + aoff + 8192 + sa, a1[0], a1[1], a1[2], a1[3]);
                ldsm_x4(sb + bbase + boff + so,        bb[0], bb[1], bb[2], bb[3]);
                mma_f16(acc[0][0], a0[0], a0[1], a0[2], a0[3], bb[0], bb[1]);
                mma_f16(acc[0][1], a0[0], a0[1], a0[2], a0[3], bb[2], bb[3]);
                mma_f16(acc[1][0], a1[0], a1[1], a1[2], a1[3], bb[0], bb[1]);
                mma_f16(acc[1][1], a1[0], a1[1], a1[2], a1[3], bb[2], bb[3]);
            }

            // fold h -> relu(h+b1).W2 into per-row partials
            int colb = ch * 64 + nw * 16 + 2 * t;
            #pragma unroll
            for (int nt = 0; nt < 2; nt++) {
                float bv0 = smB1[colb + nt * 8], bv1 = smB1[colb + nt * 8 + 1];
                float wv0 = smW2[colb + nt * 8], wv1 = smW2[colb + nt * 8 + 1];
                #pragma unroll
                for (int mt = 0; mt < 2; mt++) {
                    part[mt * 2 + 0] += fmaxf(acc[mt][nt][0] + bv0, 0.f) * wv0
                                      + fmaxf(acc[mt][nt][1] + bv1, 0.f) * wv1;
                    part[mt * 2 + 1] += fmaxf(acc[mt][nt][2] + bv0, 0.f) * wv0
                                      + fmaxf(acc[mt][nt][3] + bv1, 0.f) * wv1;
                }
            }

            // convert + store next tile's A quarter (other buffer, no hazard)
            if (havenext) {
                uint4 hv;
                hv.x = pack_h2(av0a.x, av0a.y); hv.y = pack_h2(av0a.z, av0a.w);
                hv.z = pack_h2(av1a.x, av1a.y); hv.w = pack_h2(av1a.z, av1a.w);
                *(uint4*)(smem + anext + rowA * 512 + ((cA ^ (rowA & 7)) << 4)) = hv;
                xon[rowA * 32 + cA] = hv;
                hv.x = pack_h2(av0b.x, av0b.y); hv.y = pack_h2(av0b.z, av0b.w);
                hv.z = pack_h2(av1b.x, av1b.y); hv.w = pack_h2(av1b.z, av1b.w);
                *(uint4*)(smem + anext + rowB * 512 + ((cB ^ (rowB & 7)) << 4)) = hv;
                xon[rowB * 32 + cB] = hv;
            }
        }

        // reduce over 4 lanes sharing each row, accumulate into smem
        #pragma unroll
        for (int p = 0; p < 4; p++) {
            part[p] += __shfl_xor_sync(0xffffffffu, part[p], 1);
            part[p] += __shfl_xor_sync(0xffffffffu, part[p], 2);
        }
        if (t == 0) {
            atomicAdd(&sc[mw * 32 + g],      part[0]);
            atomicAdd(&sc[mw * 32 + 8 + g],  part[1]);
            atomicAdd(&sc[mw * 32 + 16 + g], part[2]);
            atomicAdd(&sc[mw * 32 + 24 + g], part[3]);
        }
        __syncthreads();                          // atomics done
        if (tid < 128) {
            g_scores[(size_t)tile * 128 + tid] = sc[tid] + b2v;
            sc[tid] = 0.f;                        // next tile's chunk0 barrier
        }                                         // orders this vs new atomics
        cur ^= 1;
    }
}

// ---------------- kernel 4: segment softmax + weighted pooling (fp16 x) -----
__global__ void __launch_bounds__(256)
k_pool(float* __restrict__ out) {
    __shared__ float wbuf[1024];
    __shared__ float red[256];
    __shared__ float red2x[128];
    __shared__ float red2y[128];
    int g = blockIdx.x, t = threadIdx.x;
    int rp = t >> 7, cp = t & 127;
    int s0 = g_segstart[g], s1 = g_segstart[g + 1];

    float m = 0.f;
    for (int i = s0 + t; i < s1; i += 256) m = fmaxf(m, g_scores[i]);
    red[t] = m; __syncthreads();
    #pragma unroll
    for (int st = 128; st > 0; st >>= 1) {
        if (t < st) red[t] = fmaxf(red[t], red[t + st]);
        __syncthreads();
    }
    m = red[0]; __syncthreads();

    float den = 0.f;
    float ax0 = 0.f, ay0 = 0.f, ax1 = 0.f, ay1 = 0.f;
    const __half2* xh2 = (const __half2*)g_xh;
    for (int base = s0; base < s1; base += 1024) {
        int n = min(1024, s1 - base);
        for (int i = t; i < n; i += 256) {
            float e = __expf(g_scores[base + i] - m);
            wbuf[i] = e;
            den += e;
        }
        __syncthreads();
        const __half2* xb = xh2 + (size_t)base * 128 + cp;
        int i = rp;
        for (; i + 2 < n; i += 4) {
            float2 v0 = __half22float2(xb[(size_t)i * 128]);
            float2 v1 = __half22float2(xb[(size_t)(i + 2) * 128]);
            float w0 = wbuf[i], w1 = wbuf[i + 2];
            ax0 = fmaf(v0.x, w0, ax0); ay0 = fmaf(v0.y, w0, ay0);
            ax1 = fmaf(v1.x, w1, ax1); ay1 = fmaf(v1.y, w1, ay1);
        }
        for (; i < n; i += 2) {
            float2 v = __half22float2(xb[(size_t)i * 128]);
            float w = wbuf[i];
            ax0 = fmaf(v.x, w, ax0); ay0 = fmaf(v.y, w, ay0);
        }
        __syncthreads();
    }
    float ax = ax0 + ax1, ay = ay0 + ay1;

    red[t] = den; __syncthreads();
    #pragma unroll
    for (int st = 128; st > 0; st >>= 1) {
        if (t < st) red[t] += red[t + st];
        __syncthreads();
    }
    den = red[0] + 1e-9f;
    __syncthreads();

    if (rp == 1) { red2x[cp] = ax; red2y[cp] = ay; }
    __syncthreads();
    if (rp == 0) {
        out[g * 256 + 2 * cp]     = (ax + red2x[cp]) / den;
        out[g * 256 + 2 * cp + 1] = (ay + red2y[cp]) / den;
    }
}

// ---------------- launch ----------------------------------------------------
extern "C" void kernel_launch(void* const* d_in, const int* in_sizes, int n_in,
                              void* d_out, int out_size) {
    const float* x = 0; const float* W1 = 0; const float* b1 = 0;
    const float* W2 = 0; const float* b2 = 0; const void* batch = 0;
    for (int i = 0; i < n_in; i++) {
        switch (in_sizes[i]) {
            case 67108864: x = (const float*)d_in[i]; break;
            case 65536:    W1 = (const float*)d_in[i]; break;
            case 262144:   batch = d_in[i]; break;
            case 1:        b2 = (const float*)d_in[i]; break;
            case 256:
                if (!b1) b1 = (const float*)d_in[i];
                else     W2 = (const float*)d_in[i];
                break;
            default: break;
        }
    }
    if (!x)     x     = (const float*)d_in[0];
    if (!W1)    W1    = (const float*)d_in[1];
    if (!b1)    b1    = (const float*)d_in[2];
    if (!W2)    W2    = (const float*)d_in[3];
    if (!b2)    b2    = (const float*)d_in[4];
    if (!batch) batch = d_in[5];

    int sms = 0;
    cudaDeviceGetAttribute(&sms, cudaDevAttrMultiProcessorCount, 0);
    if (sms <= 0) sms = 148;

    cudaFuncSetAttribute(k_scores, cudaFuncAttributeMaxDynamicSharedMemorySize,
                         SMEM_SCORES_TOTAL);

    k_w1t<<<KDIM, HID>>>(W1);
    k_bounds<<<5, 256>>>(batch);
    k_scores<<<sms, 512, SMEM_SCORES_TOTAL>>>(x, b1, W2, b2);
    k_pool<<<NSEG, 256>>>((float*)d_out);
}